// round 2
// baseline (speedup 1.0000x reference)
#include <cuda_runtime.h>

typedef unsigned long long ULL;

// ---------------- f32x2 helpers ----------------
__device__ __forceinline__ ULL pk2(float lo, float hi) {
    ULL r; asm("mov.b64 %0, {%1,%2};" : "=l"(r) : "f"(lo), "f"(hi)); return r;
}
__device__ __forceinline__ void upk2(ULL v, float& lo, float& hi) {
    asm("mov.b64 {%0,%1}, %2;" : "=f"(lo), "=f"(hi) : "l"(v));
}
__device__ __forceinline__ ULL fma2_(ULL a, ULL b, ULL c) {
    ULL d; asm("fma.rn.f32x2 %0, %1, %2, %3;" : "=l"(d) : "l"(a), "l"(b), "l"(c)); return d;
}

// ---------------- MUFU-free softplus + sigmoid ----------------
// u = exp(-|x|) via exp2 poly with magic-number rounding;
// softplus(x) = max(x,0) + log1p(u), log1p(u) = 2*atanh(u/(2+u)) (series);
// sigmoid(x) = (x>=0 ? 1 : u) / (1+u) via Newton reciprocal.  All FMA/ALU pipe.
__device__ __forceinline__ void act1(float x, float& sp, float& sg) {
    float a = fminf(fabsf(x), 80.0f);
    float y = a * -1.4426950408889634f;          // -a*log2(e), in [-115.5, 0]
    float zz = y + 12582912.0f;                  // round-to-nearest-int magic (1.5*2^23)
    float nf = zz - 12582912.0f;
    float f  = y - nf;                           // f in [-0.5, 0.5]
    int ib = __float_as_int(zz);
    float scale = __int_as_float((int)(((unsigned)(ib + (127 - 0x4B400000))) << 23)); // 2^n
    float p = 1.33335581e-3f;
    p = fmaf(p, f, 9.61812910e-3f);
    p = fmaf(p, f, 5.55041087e-2f);
    p = fmaf(p, f, 2.40226507e-1f);
    p = fmaf(p, f, 6.93147182e-1f);
    p = fmaf(p, f, 1.0f);
    float u = p * scale;                          // exp(-a) in (0, 1]
    // r1 = 1/(1+u), d1 in [1,2]: minimax linear init + 3 Newton
    float d1 = 1.0f + u;
    float r1 = fmaf(d1, -0.5f, 1.45710678f);
    r1 = r1 * (2.0f - d1 * r1);
    r1 = r1 * (2.0f - d1 * r1);
    r1 = r1 * (2.0f - d1 * r1);
    // r2 = 1/(2+u), d2 in [2,3]: minimax linear init + 2 Newton
    float d2 = 2.0f + u;
    float r2 = fmaf(d2, -0.16666667f, 0.82491498f);
    r2 = r2 * (2.0f - d2 * r2);
    r2 = r2 * (2.0f - d2 * r2);
    // log1p(u) = 2*atanh(s), s = u/(2+u) in [0, 1/3]
    float s  = u * r2;
    float s2 = s * s;
    float q = 0.11111111f;                        // 1/9
    q = fmaf(q, s2, 0.14285714f);                 // 1/7
    q = fmaf(q, s2, 0.2f);                        // 1/5
    q = fmaf(q, s2, 0.33333333f);                 // 1/3
    q = fmaf(q, s2, 1.0f);
    float l1p = (s + s) * q;
    sp = fmaxf(x, 0.0f) + l1p;
    sg = r1 * ((x >= 0.0f) ? 1.0f : u);
}

// ---------------- shared-memory weight layout ----------------
// w2g[(j2*16 + k2)*3 + slot] (ulonglong2 = 4 packed fp32 weights):
//   slot0 (P): { W2[j2][1+4k2..+3] }                       primal
//   slot1 (A): P * W1[col z0] per-k                        tangent e0 (folded)
//   slot2 (B): P * W1[col z1] per-k                        tangent e1 (folded)
struct SmemW {
    ulonglong2 w2g[64 * 48];   // 49152 B
    float4 w1v[64];            // {W1_t, W1_z0, W1_z1, b1}
    ULL w2tb[64];              // {W2[j2][0], b2[j2]}
    ULL w3q[64];               // {W3[0][1+j], W3[1][1+j]}
    float w3t0, w3t1, b30, b31;
};

// ---------------- one dynamics evaluation ----------------
__device__ __forceinline__ void eval_dyn(const SmemW& sm, float t, float z0, float z1,
                                         float& k0, float& k1, float& kl)
{
    ULL s1p[32], sgp[32];    // packed {even, odd} softplus / sigmoid of layer-1
    #pragma unroll
    for (int k = 0; k < 32; ++k) {
        float4 wA = sm.w1v[2 * k];
        float4 wB = sm.w1v[2 * k + 1];
        float xa = fmaf(wA.x, t, wA.w); xa = fmaf(wA.y, z0, xa); xa = fmaf(wA.z, z1, xa);
        float xb = fmaf(wB.x, t, wB.w); xb = fmaf(wB.y, z0, xb); xb = fmaf(wB.z, z1, xb);
        float spa, sga, spb, sgb;
        act1(xa, spa, sga);
        act1(xb, spb, sgb);
        s1p[k] = pk2(spa, spb);
        sgp[k] = pk2(sga, sgb);
    }

    float zd0 = fmaf(sm.w3t0, t, sm.b30);
    float zd1 = fmaf(sm.w3t1, t, sm.b31);
    float tr = 0.0f;

    #pragma unroll 1
    for (int j2 = 0; j2 < 64; ++j2) {
        float w2t, b2v; upk2(sm.w2tb[j2], w2t, b2v);
        ULL accp = pk2(fmaf(w2t, t, b2v), 0.0f);
        ULL acca = pk2(0.0f, 0.0f);
        ULL accb = pk2(0.0f, 0.0f);
        const ulonglong2* rowp = &sm.w2g[j2 * 48];
        #pragma unroll
        for (int k2 = 0; k2 < 16; ++k2) {
            ulonglong2 P  = rowp[k2 * 3 + 0];
            ulonglong2 A  = rowp[k2 * 3 + 1];
            ulonglong2 Bv = rowp[k2 * 3 + 2];
            accp = fma2_(P.x,  s1p[2 * k2],     accp);
            accp = fma2_(P.y,  s1p[2 * k2 + 1], accp);
            acca = fma2_(A.x,  sgp[2 * k2],     acca);
            acca = fma2_(A.y,  sgp[2 * k2 + 1], acca);
            accb = fma2_(Bv.x, sgp[2 * k2],     accb);
            accb = fma2_(Bv.y, sgp[2 * k2 + 1], accb);
        }
        float pl, ph; upk2(accp, pl, ph); float h2  = pl + ph;   // layer-2 preact
        float al, ah; upk2(acca, al, ah); float ta  = al + ah;   // tangent-a preact
        float bl, bh; upk2(accb, bl, bh); float tbv = bl + bh;   // tangent-b preact
        float sp2, sg2; act1(h2, sp2, sg2);
        float w30, w31; upk2(sm.w3q[j2], w30, w31);
        zd0 = fmaf(w30, sp2, zd0);
        zd1 = fmaf(w31, sp2, zd1);
        float td = w30 * ta; td = fmaf(w31, tbv, td);
        tr = fmaf(sg2, td, tr);
    }
    k0 = zd0; k1 = zd1; kl = -tr;   // delta_logpz integrand = -divergence
}

__global__ void __launch_bounds__(128) ffjord_kernel(
    const float2* __restrict__ zin, const float* __restrict__ dlp,
    const float* __restrict__ W1, const float* __restrict__ b1,
    const float* __restrict__ W2, const float* __restrict__ b2,
    const float* __restrict__ W3, const float* __restrict__ b3,
    float* __restrict__ out, int B)
{
    extern __shared__ unsigned char smraw[];
    SmemW& sm = *reinterpret_cast<SmemW*>(smraw);
    int tid = threadIdx.x;

    // ---- stage weights into smem (tangent columns folded into layer-2) ----
    for (int idx = tid; idx < 1024; idx += 128) {
        int j2 = idx >> 4, k2 = idx & 15;
        int bb = 4 * k2;
        const float* wr = W2 + j2 * 65 + 1;          // skip time col
        float p0 = wr[bb + 0], p1 = wr[bb + 1], p2 = wr[bb + 2], p3 = wr[bb + 3];
        float a0 = W1[(bb + 0) * 3 + 1], a1 = W1[(bb + 1) * 3 + 1];
        float a2 = W1[(bb + 2) * 3 + 1], a3 = W1[(bb + 3) * 3 + 1];
        float c0 = W1[(bb + 0) * 3 + 2], c1 = W1[(bb + 1) * 3 + 2];
        float c2 = W1[(bb + 2) * 3 + 2], c3 = W1[(bb + 3) * 3 + 2];
        ulonglong2 P, A, Bv;
        P.x  = pk2(p0, p1);           P.y  = pk2(p2, p3);
        A.x  = pk2(p0 * a0, p1 * a1); A.y  = pk2(p2 * a2, p3 * a3);
        Bv.x = pk2(p0 * c0, p1 * c1); Bv.y = pk2(p2 * c2, p3 * c3);
        sm.w2g[(j2 * 16 + k2) * 3 + 0] = P;
        sm.w2g[(j2 * 16 + k2) * 3 + 1] = A;
        sm.w2g[(j2 * 16 + k2) * 3 + 2] = Bv;
    }
    if (tid < 64) {
        int j = tid;
        sm.w1v[j]  = make_float4(W1[j * 3 + 0], W1[j * 3 + 1], W1[j * 3 + 2], b1[j]);
        sm.w2tb[j] = pk2(W2[j * 65 + 0], b2[j]);
        sm.w3q[j]  = pk2(W3[1 + j], W3[66 + j]);
    }
    if (tid == 0) { sm.w3t0 = W3[0]; sm.w3t1 = W3[65]; sm.b30 = b3[0]; sm.b31 = b3[1]; }
    __syncthreads();

    int gid = blockIdx.x * 128 + tid;
    if (gid >= B) return;
    float2 zv = zin[gid];
    float z0 = zv.x, z1 = zv.y;
    float lp = dlp[gid];

    const float dt = 0.25f;
    #pragma unroll 1
    for (int step = 0; step < 4; ++step) {
        float tb0 = (float)step * dt;
        float acc0 = 0.0f, acc1 = 0.0f, accl = 0.0f;
        float pk0v = 0.0f, pk1v = 0.0f;
        #pragma unroll 1
        for (int s = 0; s < 4; ++s) {
            float cs = (s == 0) ? 0.0f : ((s == 3) ? dt : 0.5f * dt);
            float ws = (s == 1 || s == 2) ? 2.0f : 1.0f;
            float te = tb0 + cs;
            float i0 = fmaf(cs, pk0v, z0);
            float i1 = fmaf(cs, pk1v, z1);
            float k0, k1, klv;
            eval_dyn(sm, te, i0, i1, k0, k1, klv);
            acc0 = fmaf(ws, k0, acc0);
            acc1 = fmaf(ws, k1, acc1);
            accl = fmaf(ws, klv, accl);
            pk0v = k0; pk1v = k1;
        }
        const float c6 = dt / 6.0f;
        z0 = fmaf(c6, acc0, z0);
        z1 = fmaf(c6, acc1, z1);
        lp = fmaf(c6, accl, lp);
    }

    reinterpret_cast<float2*>(out)[gid] = make_float2(z0, z1);  // zf: (B,2)
    out[2 * B + gid] = lp;                                      // delta_logpz: (B,1)
}

extern "C" void kernel_launch(void* const* d_in, const int* in_sizes, int n_in,
                              void* d_out, int out_size) {
    const float2* z  = (const float2*)d_in[0];
    const float* dlp = (const float*)d_in[1];
    const float* W1  = (const float*)d_in[2];
    const float* b1  = (const float*)d_in[3];
    const float* W2  = (const float*)d_in[4];
    const float* b2  = (const float*)d_in[5];
    const float* W3  = (const float*)d_in[6];
    const float* b3  = (const float*)d_in[7];
    float* out = (float*)d_out;
    int B = in_sizes[0] / 2;

    static int smem_set = 0;
    // cudaFuncSetAttribute is host-side and idempotent; it enqueues nothing,
    // so it is graph-capture-safe. Called unconditionally for determinism.
    cudaFuncSetAttribute(ffjord_kernel, cudaFuncAttributeMaxDynamicSharedMemorySize,
                         (int)sizeof(SmemW));
    (void)smem_set;

    int blocks = (B + 127) / 128;
    ffjord_kernel<<<blocks, 128, sizeof(SmemW)>>>(z, dlp, W1, b1, W2, b2, W3, b3, out, B);
}

// round 3
// speedup vs baseline: 1.2456x; 1.2456x over previous
#include <cuda_runtime.h>

typedef unsigned long long ULL;

// ---------------- f32x2 helpers ----------------
__device__ __forceinline__ ULL pk2(float lo, float hi) {
    ULL r; asm("mov.b64 %0, {%1,%2};" : "=l"(r) : "f"(lo), "f"(hi)); return r;
}
__device__ __forceinline__ void upk2(ULL v, float& lo, float& hi) {
    asm("mov.b64 {%0,%1}, %2;" : "=f"(lo), "=f"(hi) : "l"(v));
}
__device__ __forceinline__ ULL fma2_(ULL a, ULL b, ULL c) {
    ULL d; asm("fma.rn.f32x2 %0, %1, %2, %3;" : "=l"(d) : "l"(a), "l"(b), "l"(c)); return d;
}

// ---------------- MUFU-free softplus + sigmoid ----------------
// u = exp(-|x|) via exp2 poly with magic-number rounding;
// softplus(x) = max(x,0) + log1p(u), log1p(u) = 2*atanh(u/(2+u)) (series);
// sigmoid(x) = (x>=0 ? 1 : u) / (1+u) via Newton reciprocal.  All FMA/ALU pipe.
__device__ __forceinline__ void act1(float x, float& sp, float& sg) {
    float a = fminf(fabsf(x), 80.0f);
    float y = a * -1.4426950408889634f;          // -a*log2(e)
    float zz = y + 12582912.0f;                  // round-to-nearest-int magic
    float nf = zz - 12582912.0f;
    float f  = y - nf;                           // f in [-0.5, 0.5]
    int ib = __float_as_int(zz);
    float scale = __int_as_float((int)(((unsigned)(ib + (127 - 0x4B400000))) << 23)); // 2^n
    float p = 1.33335581e-3f;
    p = fmaf(p, f, 9.61812910e-3f);
    p = fmaf(p, f, 5.55041087e-2f);
    p = fmaf(p, f, 2.40226507e-1f);
    p = fmaf(p, f, 6.93147182e-1f);
    p = fmaf(p, f, 1.0f);
    float u = p * scale;                          // exp(-a) in (0, 1]
    float d1 = 1.0f + u;
    float r1 = fmaf(d1, -0.5f, 1.45710678f);      // 1/(1+u): init + 3 Newton
    r1 = r1 * (2.0f - d1 * r1);
    r1 = r1 * (2.0f - d1 * r1);
    r1 = r1 * (2.0f - d1 * r1);
    float d2 = 2.0f + u;
    float r2 = fmaf(d2, -0.16666667f, 0.82491498f);  // 1/(2+u): init + 2 Newton
    r2 = r2 * (2.0f - d2 * r2);
    r2 = r2 * (2.0f - d2 * r2);
    float s  = u * r2;                            // s in [0, 1/3]
    float s2 = s * s;
    float q = 0.11111111f;
    q = fmaf(q, s2, 0.14285714f);
    q = fmaf(q, s2, 0.2f);
    q = fmaf(q, s2, 0.33333333f);
    q = fmaf(q, s2, 1.0f);
    float l1p = (s + s) * q;                      // log1p(u)
    sp = fmaxf(x, 0.0f) + l1p;
    sg = r1 * ((x >= 0.0f) ? 1.0f : u);
}

// ---------------- shared-memory weight layout ----------------
// w2g[(j2*16 + k2)*3 + slot] (ulonglong2 = 4 packed fp32 weights):
//   slot0 (P): { W2[j2][1+4k2..+3] }          primal
//   slot1 (A): P * W1[col z0] per-k           tangent e0 (folded)
//   slot2 (B): P * W1[col z1] per-k           tangent e1 (folded)
struct SmemW {
    ulonglong2 w2g[64 * 48];   // 49152 B
    float4 w1v[64];            // {W1_t, W1_z0, W1_z1, b1}
    ULL w2tb[64];              // {W2[j2][0], b2[j2]}
    ULL w3q[64];               // {W3[0][1+j], W3[1][1+j]}
    float w3t0, w3t1, b30, b31;
};

// ---------------- one dynamics evaluation ----------------
__device__ __forceinline__ void eval_dyn(const SmemW& sm, float t, float z0, float z1,
                                         float& k0, float& k1, float& kl)
{
    ULL s1p[32], sgp[32];    // packed {even, odd} softplus / sigmoid of layer-1
    #pragma unroll 8
    for (int k = 0; k < 32; ++k) {
        float4 wA = sm.w1v[2 * k];
        float4 wB = sm.w1v[2 * k + 1];
        float xa = fmaf(wA.x, t, wA.w); xa = fmaf(wA.y, z0, xa); xa = fmaf(wA.z, z1, xa);
        float xb = fmaf(wB.x, t, wB.w); xb = fmaf(wB.y, z0, xb); xb = fmaf(wB.z, z1, xb);
        float spa, sga, spb, sgb;
        act1(xa, spa, sga);
        act1(xb, spb, sgb);
        s1p[k] = pk2(spa, spb);
        sgp[k] = pk2(sga, sgb);
    }

    float zd0 = fmaf(sm.w3t0, t, sm.b30);
    float zd1 = fmaf(sm.w3t1, t, sm.b31);
    float tr = 0.0f;

    // Two output units per iteration: doubles FMA-chain ILP in the inner loop
    // and gives the layer-2 activation phase two independent chains per warp.
    #pragma unroll 1
    for (int j2 = 0; j2 < 64; j2 += 2) {
        float w2t0, b2v0; upk2(sm.w2tb[j2],     w2t0, b2v0);
        float w2t1, b2v1; upk2(sm.w2tb[j2 + 1], w2t1, b2v1);
        ULL accp0 = pk2(fmaf(w2t0, t, b2v0), 0.0f);
        ULL accp1 = pk2(fmaf(w2t1, t, b2v1), 0.0f);
        ULL acca0 = pk2(0.0f, 0.0f), acca1 = pk2(0.0f, 0.0f);
        ULL accb0 = pk2(0.0f, 0.0f), accb1 = pk2(0.0f, 0.0f);
        const ulonglong2* r0 = &sm.w2g[j2 * 48];
        #pragma unroll 2
        for (int k2 = 0; k2 < 16; ++k2) {
            ulonglong2 P0  = r0[k2 * 3 + 0];
            ulonglong2 A0  = r0[k2 * 3 + 1];
            ulonglong2 B0  = r0[k2 * 3 + 2];
            ulonglong2 P1  = r0[48 + k2 * 3 + 0];
            ulonglong2 A1  = r0[48 + k2 * 3 + 1];
            ulonglong2 B1  = r0[48 + k2 * 3 + 2];
            ULL se = s1p[2 * k2], so = s1p[2 * k2 + 1];
            ULL ge = sgp[2 * k2], go = sgp[2 * k2 + 1];
            accp0 = fma2_(P0.x, se, accp0);  accp0 = fma2_(P0.y, so, accp0);
            accp1 = fma2_(P1.x, se, accp1);  accp1 = fma2_(P1.y, so, accp1);
            acca0 = fma2_(A0.x, ge, acca0);  acca0 = fma2_(A0.y, go, acca0);
            acca1 = fma2_(A1.x, ge, acca1);  acca1 = fma2_(A1.y, go, acca1);
            accb0 = fma2_(B0.x, ge, accb0);  accb0 = fma2_(B0.y, go, accb0);
            accb1 = fma2_(B1.x, ge, accb1);  accb1 = fma2_(B1.y, go, accb1);
        }
        float pl, ph;
        upk2(accp0, pl, ph); float h20  = pl + ph;
        upk2(accp1, pl, ph); float h21  = pl + ph;
        upk2(acca0, pl, ph); float ta0  = pl + ph;
        upk2(acca1, pl, ph); float ta1  = pl + ph;
        upk2(accb0, pl, ph); float tb0  = pl + ph;
        upk2(accb1, pl, ph); float tb1  = pl + ph;
        float sp20, sg20, sp21, sg21;
        act1(h20, sp20, sg20);       // two independent dependency chains
        act1(h21, sp21, sg21);
        float w300, w310; upk2(sm.w3q[j2],     w300, w310);
        float w301, w311; upk2(sm.w3q[j2 + 1], w301, w311);
        zd0 = fmaf(w300, sp20, zd0); zd0 = fmaf(w301, sp21, zd0);
        zd1 = fmaf(w310, sp20, zd1); zd1 = fmaf(w311, sp21, zd1);
        float td0 = w300 * ta0; td0 = fmaf(w310, tb0, td0);
        float td1 = w301 * ta1; td1 = fmaf(w311, tb1, td1);
        tr = fmaf(sg20, td0, tr);
        tr = fmaf(sg21, td1, tr);
    }
    k0 = zd0; k1 = zd1; kl = -tr;   // delta_logpz integrand = -divergence
}

__global__ void __launch_bounds__(128, 3) ffjord_kernel(
    const float2* __restrict__ zin, const float* __restrict__ dlp,
    const float* __restrict__ W1, const float* __restrict__ b1,
    const float* __restrict__ W2, const float* __restrict__ b2,
    const float* __restrict__ W3, const float* __restrict__ b3,
    float* __restrict__ out, int B)
{
    extern __shared__ unsigned char smraw[];
    SmemW& sm = *reinterpret_cast<SmemW*>(smraw);
    int tid = threadIdx.x;

    // ---- stage weights into smem (tangent columns folded into layer-2) ----
    for (int idx = tid; idx < 1024; idx += 128) {
        int j2 = idx >> 4, k2 = idx & 15;
        int bb = 4 * k2;
        const float* wr = W2 + j2 * 65 + 1;          // skip time col
        float p0 = wr[bb + 0], p1 = wr[bb + 1], p2 = wr[bb + 2], p3 = wr[bb + 3];
        float a0 = W1[(bb + 0) * 3 + 1], a1 = W1[(bb + 1) * 3 + 1];
        float a2 = W1[(bb + 2) * 3 + 1], a3 = W1[(bb + 3) * 3 + 1];
        float c0 = W1[(bb + 0) * 3 + 2], c1 = W1[(bb + 1) * 3 + 2];
        float c2 = W1[(bb + 2) * 3 + 2], c3 = W1[(bb + 3) * 3 + 2];
        ulonglong2 P, A, Bv;
        P.x  = pk2(p0, p1);           P.y  = pk2(p2, p3);
        A.x  = pk2(p0 * a0, p1 * a1); A.y  = pk2(p2 * a2, p3 * a3);
        Bv.x = pk2(p0 * c0, p1 * c1); Bv.y = pk2(p2 * c2, p3 * c3);
        sm.w2g[(j2 * 16 + k2) * 3 + 0] = P;
        sm.w2g[(j2 * 16 + k2) * 3 + 1] = A;
        sm.w2g[(j2 * 16 + k2) * 3 + 2] = Bv;
    }
    if (tid < 64) {
        int j = tid;
        sm.w1v[j]  = make_float4(W1[j * 3 + 0], W1[j * 3 + 1], W1[j * 3 + 2], b1[j]);
        sm.w2tb[j] = pk2(W2[j * 65 + 0], b2[j]);
        sm.w3q[j]  = pk2(W3[1 + j], W3[66 + j]);
    }
    if (tid == 0) { sm.w3t0 = W3[0]; sm.w3t1 = W3[65]; sm.b30 = b3[0]; sm.b31 = b3[1]; }
    __syncthreads();

    int gid = blockIdx.x * 128 + tid;
    if (gid >= B) return;
    float2 zv = zin[gid];
    float z0 = zv.x, z1 = zv.y;
    float lp = dlp[gid];

    const float dt = 0.25f;
    #pragma unroll 1
    for (int step = 0; step < 4; ++step) {
        float tb = (float)step * dt;
        float acc0 = 0.0f, acc1 = 0.0f, accl = 0.0f;
        float pk0v = 0.0f, pk1v = 0.0f;
        #pragma unroll 1
        for (int s = 0; s < 4; ++s) {
            float cs = (s == 0) ? 0.0f : ((s == 3) ? dt : 0.5f * dt);
            float ws = (s == 1 || s == 2) ? 2.0f : 1.0f;
            float te = tb + cs;
            float i0 = fmaf(cs, pk0v, z0);
            float i1 = fmaf(cs, pk1v, z1);
            float k0, k1, klv;
            eval_dyn(sm, te, i0, i1, k0, k1, klv);
            acc0 = fmaf(ws, k0, acc0);
            acc1 = fmaf(ws, k1, acc1);
            accl = fmaf(ws, klv, accl);
            pk0v = k0; pk1v = k1;
        }
        const float c6 = dt / 6.0f;
        z0 = fmaf(c6, acc0, z0);
        z1 = fmaf(c6, acc1, z1);
        lp = fmaf(c6, accl, lp);
    }

    reinterpret_cast<float2*>(out)[gid] = make_float2(z0, z1);  // zf: (B,2)
    out[2 * B + gid] = lp;                                      // delta_logpz: (B,1)
}

extern "C" void kernel_launch(void* const* d_in, const int* in_sizes, int n_in,
                              void* d_out, int out_size) {
    const float2* z  = (const float2*)d_in[0];
    const float* dlp = (const float*)d_in[1];
    const float* W1  = (const float*)d_in[2];
    const float* b1  = (const float*)d_in[3];
    const float* W2  = (const float*)d_in[4];
    const float* b2  = (const float*)d_in[5];
    const float* W3  = (const float*)d_in[6];
    const float* b3  = (const float*)d_in[7];
    float* out = (float*)d_out;
    int B = in_sizes[0] / 2;

    // Host-side, enqueues nothing -> graph-capture safe. Idempotent.
    cudaFuncSetAttribute(ffjord_kernel, cudaFuncAttributeMaxDynamicSharedMemorySize,
                         (int)sizeof(SmemW));

    int blocks = (B + 127) / 128;
    ffjord_kernel<<<blocks, 128, sizeof(SmemW)>>>(z, dlp, W1, b1, W2, b2, W3, b3, out, B);
}

// round 4
// speedup vs baseline: 1.3569x; 1.0894x over previous
#include <cuda_runtime.h>

typedef unsigned long long ULL;

// ---------------- f32x2 helpers ----------------
__device__ __forceinline__ ULL pk2(float lo, float hi) {
    ULL r; asm("mov.b64 %0, {%1,%2};" : "=l"(r) : "f"(lo), "f"(hi)); return r;
}
__device__ __forceinline__ void upk2(ULL v, float& lo, float& hi) {
    asm("mov.b64 {%0,%1}, %2;" : "=f"(lo), "=f"(hi) : "l"(v));
}
__device__ __forceinline__ ULL fma2_(ULL a, ULL b, ULL c) {
    ULL d; asm("fma.rn.f32x2 %0, %1, %2, %3;" : "=l"(d) : "l"(a), "l"(b), "l"(c)); return d;
}
__device__ __forceinline__ ULL add2_(ULL a, ULL b) {
    ULL d; asm("add.rn.f32x2 %0, %1, %2;" : "=l"(d) : "l"(a), "l"(b)); return d;
}
__device__ __forceinline__ ULL mul2_(ULL a, ULL b) {
    ULL d; asm("mul.rn.f32x2 %0, %1, %2;" : "=l"(d) : "l"(a), "l"(b)); return d;
}

// ---------------- packed MUFU-free softplus + sigmoid (2 lanes) ----------------
// u = exp(-|x|) via exp2 poly (magic rounding); softplus = max(x,0)+log1p(u)
// with log1p(u)=2*atanh(u/(2+u)); sigmoid = (x>=0?1:u)/(1+u) via Newton rcp.
__device__ __forceinline__ void act2(float xa, float xb, ULL& sp, ULL& sg)
{
    const ULL MAGIC = pk2(12582912.f, 12582912.f);
    const ULL NEG1  = pk2(-1.f, -1.f);
    const ULL ONE   = pk2(1.f, 1.f);
    const ULL TWO   = pk2(2.f, 2.f);
    const ULL C5 = pk2(1.33335581e-3f, 1.33335581e-3f);
    const ULL C4 = pk2(9.61812910e-3f, 9.61812910e-3f);
    const ULL C3 = pk2(5.55041087e-2f, 5.55041087e-2f);
    const ULL C2 = pk2(2.40226507e-1f, 2.40226507e-1f);
    const ULL C1 = pk2(6.93147182e-1f, 6.93147182e-1f);
    const ULL RI1 = pk2(-0.5f, -0.5f);
    const ULL RK1 = pk2(1.45710678f, 1.45710678f);
    const ULL RI2 = pk2(-0.16666667f, -0.16666667f);
    const ULL RK2 = pk2(0.82491498f, 0.82491498f);
    const ULL A7 = pk2(0.14285714f, 0.14285714f);
    const ULL A5 = pk2(0.2f, 0.2f);
    const ULL A3 = pk2(0.33333333f, 0.33333333f);

    float ya = fmaxf(fabsf(xa) * -1.4426950408889634f, -116.0f);
    float yb = fmaxf(fabsf(xb) * -1.4426950408889634f, -116.0f);
    ULL y  = pk2(ya, yb);
    ULL zz = add2_(y, MAGIC);
    ULL nf = fma2_(MAGIC, NEG1, zz);       // zz - MAGIC
    ULL f  = fma2_(nf, NEG1, y);           // y - nf, in [-0.5, 0.5]
    float za, zb2; upk2(zz, za, zb2);
    int ia = __float_as_int(za), ibt = __float_as_int(zb2);
    float sa = __int_as_float((int)(((unsigned)(ia  + (127 - 0x4B400000))) << 23));
    float sb = __int_as_float((int)(((unsigned)(ibt + (127 - 0x4B400000))) << 23));
    ULL scale = pk2(sa, sb);
    ULL p = fma2_(C5, f, C4);
    p = fma2_(p, f, C3);
    p = fma2_(p, f, C2);
    p = fma2_(p, f, C1);
    p = fma2_(p, f, ONE);
    ULL u = mul2_(p, scale);               // exp(-|x|) in (0,1]
    // r1 = 1/(1+u): linear minimax init + 2 Newton (rel err ~3e-6)
    ULL d1 = add2_(u, ONE);
    ULL r1 = fma2_(d1, RI1, RK1);
    ULL nd1 = mul2_(d1, NEG1);
    ULL m;
    m = fma2_(nd1, r1, TWO); r1 = mul2_(r1, m);
    m = fma2_(nd1, r1, TWO); r1 = mul2_(r1, m);
    // r2 = 1/(2+u): init + 2 Newton
    ULL d2 = add2_(u, TWO);
    ULL r2 = fma2_(d2, RI2, RK2);
    ULL nd2 = mul2_(d2, NEG1);
    m = fma2_(nd2, r2, TWO); r2 = mul2_(r2, m);
    m = fma2_(nd2, r2, TWO); r2 = mul2_(r2, m);
    // log1p(u) = 2*atanh(s), s = u/(2+u) in [0,1/3]; series to s^7 (err ~1e-5)
    ULL s  = mul2_(u, r2);
    ULL s2 = mul2_(s, s);
    ULL q = fma2_(A7, s2, A5);
    q = fma2_(q, s2, A3);
    q = fma2_(q, s2, ONE);
    ULL l1p = mul2_(add2_(s, s), q);
    float mxa = fmaxf(xa, 0.f), mxb = fmaxf(xb, 0.f);
    sp = add2_(pk2(mxa, mxb), l1p);
    float ulo, uhi; upk2(u, ulo, uhi);
    float ga = (xa >= 0.f) ? 1.f : ulo;
    float gb = (xb >= 0.f) ? 1.f : uhi;
    sg = mul2_(r1, pk2(ga, gb));
}

// ---------------- shared-memory weight layout ----------------
// w2g[(j2*16 + k2)*3 + slot] (ulonglong2 = 4 packed fp32 weights):
//   slot0 (P): W2[j2][1+4k2..+3]      primal
//   slot1 (A): P * W1[col z0]         tangent e0 (folded)
//   slot2 (B): P * W1[col z1]         tangent e1 (folded)
struct SmemW {
    ulonglong2 w2g[64 * 48];           // 49152 B
    ULL w1t[32], w1z0[32], w1z1[32], w1b[32];   // packed per unit-pair
    ULL w2tb[64];                      // {W2[j][0], b2[j]}
    ULL w3r0[32], w3r1[32];            // {W3[0][1+2jp], W3[0][2+2jp]}, row 1
    float w3t0, w3t1, b30, b31;
};

// ---------------- one dynamics evaluation ----------------
__device__ __forceinline__ void eval_dyn(const SmemW& sm, float t, float z0, float z1,
                                         float& k0, float& k1, float& kl)
{
    ULL s1p[32], sgp[32];   // packed {even, odd} softplus / sigmoid of layer-1
    ULL tp = pk2(t, t), z0p = pk2(z0, z0), z1p = pk2(z1, z1);
    #pragma unroll
    for (int k = 0; k < 32; ++k) {
        ULL x = fma2_(sm.w1t[k], tp, sm.w1b[k]);
        x = fma2_(sm.w1z0[k], z0p, x);
        x = fma2_(sm.w1z1[k], z1p, x);
        float xa, xb; upk2(x, xa, xb);
        act2(xa, xb, s1p[k], sgp[k]);
    }

    ULL Zd0 = 0ull, Zd1 = 0ull, Tr = 0ull;   // bit pattern 0 == {0.f, 0.f}

    #pragma unroll 2
    for (int jp = 0; jp < 32; ++jp) {        // output-unit pair (2jp, 2jp+1)
        const ulonglong2* r0 = &sm.w2g[(2 * jp) * 48];
        ULL accp0 = 0ull, accp1 = 0ull;
        ULL acca0 = 0ull, acca1 = 0ull;
        ULL accb0 = 0ull, accb1 = 0ull;
        #pragma unroll
        for (int k2 = 0; k2 < 16; ++k2) {
            ulonglong2 P0 = r0[k2 * 3 + 0];
            ulonglong2 A0 = r0[k2 * 3 + 1];
            ulonglong2 B0 = r0[k2 * 3 + 2];
            ulonglong2 P1 = r0[48 + k2 * 3 + 0];
            ulonglong2 A1 = r0[48 + k2 * 3 + 1];
            ulonglong2 B1 = r0[48 + k2 * 3 + 2];
            ULL se = s1p[2 * k2], so = s1p[2 * k2 + 1];
            ULL ge = sgp[2 * k2], go = sgp[2 * k2 + 1];
            accp0 = fma2_(P0.x, se, accp0);  accp0 = fma2_(P0.y, so, accp0);
            accp1 = fma2_(P1.x, se, accp1);  accp1 = fma2_(P1.y, so, accp1);
            acca0 = fma2_(A0.x, ge, acca0);  acca0 = fma2_(A0.y, go, acca0);
            acca1 = fma2_(A1.x, ge, acca1);  acca1 = fma2_(A1.y, go, acca1);
            accb0 = fma2_(B0.x, ge, accb0);  accb0 = fma2_(B0.y, go, accb0);
            accb1 = fma2_(B1.x, ge, accb1);  accb1 = fma2_(B1.y, go, accb1);
        }
        float w2ta, b2a; upk2(sm.w2tb[2 * jp],     w2ta, b2a);
        float w2tc, b2c; upk2(sm.w2tb[2 * jp + 1], w2tc, b2c);
        float pl, ph;
        upk2(accp0, pl, ph); float h20 = pl + ph + fmaf(w2ta, t, b2a);
        upk2(accp1, pl, ph); float h21 = pl + ph + fmaf(w2tc, t, b2c);
        upk2(acca0, pl, ph); float ta0 = pl + ph;
        upk2(acca1, pl, ph); float ta1 = pl + ph;
        upk2(accb0, pl, ph); float tb0 = pl + ph;
        upk2(accb1, pl, ph); float tb1 = pl + ph;
        ULL sp2, sg2;
        act2(h20, h21, sp2, sg2);
        ULL w30p = sm.w3r0[jp], w31p = sm.w3r1[jp];
        Zd0 = fma2_(w30p, sp2, Zd0);
        Zd1 = fma2_(w31p, sp2, Zd1);
        ULL tdp = mul2_(w30p, pk2(ta0, ta1));
        tdp = fma2_(w31p, pk2(tb0, tb1), tdp);
        Tr = fma2_(sg2, tdp, Tr);
    }
    float a, b;
    upk2(Zd0, a, b); k0 = a + b + fmaf(sm.w3t0, t, sm.b30);
    upk2(Zd1, a, b); k1 = a + b + fmaf(sm.w3t1, t, sm.b31);
    upk2(Tr,  a, b); kl = -(a + b);
}

__global__ void __launch_bounds__(128, 2) ffjord_kernel(
    const float2* __restrict__ zin, const float* __restrict__ dlp,
    const float* __restrict__ W1, const float* __restrict__ b1,
    const float* __restrict__ W2, const float* __restrict__ b2,
    const float* __restrict__ W3, const float* __restrict__ b3,
    float* __restrict__ out, int B)
{
    extern __shared__ unsigned char smraw[];
    SmemW& sm = *reinterpret_cast<SmemW*>(smraw);
    int tid = threadIdx.x;

    // ---- stage weights into smem (tangent columns folded into layer-2) ----
    for (int idx = tid; idx < 1024; idx += 128) {
        int j2 = idx >> 4, k2 = idx & 15;
        int bb = 4 * k2;
        const float* wr = W2 + j2 * 65 + 1;          // skip time column
        float p0 = wr[bb + 0], p1 = wr[bb + 1], p2 = wr[bb + 2], p3 = wr[bb + 3];
        float a0 = W1[(bb + 0) * 3 + 1], a1 = W1[(bb + 1) * 3 + 1];
        float a2 = W1[(bb + 2) * 3 + 1], a3 = W1[(bb + 3) * 3 + 1];
        float c0 = W1[(bb + 0) * 3 + 2], c1 = W1[(bb + 1) * 3 + 2];
        float c2 = W1[(bb + 2) * 3 + 2], c3 = W1[(bb + 3) * 3 + 2];
        ulonglong2 P, A, Bv;
        P.x  = pk2(p0, p1);           P.y  = pk2(p2, p3);
        A.x  = pk2(p0 * a0, p1 * a1); A.y  = pk2(p2 * a2, p3 * a3);
        Bv.x = pk2(p0 * c0, p1 * c1); Bv.y = pk2(p2 * c2, p3 * c3);
        sm.w2g[(j2 * 16 + k2) * 3 + 0] = P;
        sm.w2g[(j2 * 16 + k2) * 3 + 1] = A;
        sm.w2g[(j2 * 16 + k2) * 3 + 2] = Bv;
    }
    if (tid < 32) {
        int k = tid;                                  // unit pair (2k, 2k+1)
        sm.w1t[k]  = pk2(W1[(2 * k) * 3 + 0], W1[(2 * k + 1) * 3 + 0]);
        sm.w1z0[k] = pk2(W1[(2 * k) * 3 + 1], W1[(2 * k + 1) * 3 + 1]);
        sm.w1z1[k] = pk2(W1[(2 * k) * 3 + 2], W1[(2 * k + 1) * 3 + 2]);
        sm.w1b[k]  = pk2(b1[2 * k], b1[2 * k + 1]);
        sm.w3r0[k] = pk2(W3[1 + 2 * k],  W3[2 + 2 * k]);
        sm.w3r1[k] = pk2(W3[66 + 2 * k], W3[67 + 2 * k]);
    } else if (tid < 96) {
        int j = tid - 32;
        sm.w2tb[j] = pk2(W2[j * 65 + 0], b2[j]);
    }
    if (tid == 0) { sm.w3t0 = W3[0]; sm.w3t1 = W3[65]; sm.b30 = b3[0]; sm.b31 = b3[1]; }
    __syncthreads();

    int gid = blockIdx.x * 128 + tid;
    if (gid >= B) return;
    float2 zv = zin[gid];
    float z0 = zv.x, z1 = zv.y;
    float lp = dlp[gid];

    const float dt = 0.25f;
    #pragma unroll 1
    for (int step = 0; step < 4; ++step) {
        float tb = (float)step * dt;
        float acc0 = 0.0f, acc1 = 0.0f, accl = 0.0f;
        float pk0v = 0.0f, pk1v = 0.0f;
        #pragma unroll 1
        for (int s = 0; s < 4; ++s) {
            float cs = (s == 0) ? 0.0f : ((s == 3) ? dt : 0.5f * dt);
            float ws = (s == 1 || s == 2) ? 2.0f : 1.0f;
            float te = tb + cs;
            float i0 = fmaf(cs, pk0v, z0);
            float i1 = fmaf(cs, pk1v, z1);
            float k0, k1, klv;
            eval_dyn(sm, te, i0, i1, k0, k1, klv);
            acc0 = fmaf(ws, k0, acc0);
            acc1 = fmaf(ws, k1, acc1);
            accl = fmaf(ws, klv, accl);
            pk0v = k0; pk1v = k1;
        }
        const float c6 = dt / 6.0f;
        z0 = fmaf(c6, acc0, z0);
        z1 = fmaf(c6, acc1, z1);
        lp = fmaf(c6, accl, lp);
    }

    reinterpret_cast<float2*>(out)[gid] = make_float2(z0, z1);  // zf: (B,2)
    out[2 * B + gid] = lp;                                      // delta_logpz: (B,1)
}

extern "C" void kernel_launch(void* const* d_in, const int* in_sizes, int n_in,
                              void* d_out, int out_size) {
    const float2* z  = (const float2*)d_in[0];
    const float* dlp = (const float*)d_in[1];
    const float* W1  = (const float*)d_in[2];
    const float* b1  = (const float*)d_in[3];
    const float* W2  = (const float*)d_in[4];
    const float* b2  = (const float*)d_in[5];
    const float* W3  = (const float*)d_in[6];
    const float* b3  = (const float*)d_in[7];
    float* out = (float*)d_out;
    int B = in_sizes[0] / 2;

    // Host-side, enqueues nothing -> graph-capture safe. Idempotent.
    cudaFuncSetAttribute(ffjord_kernel, cudaFuncAttributeMaxDynamicSharedMemorySize,
                         (int)sizeof(SmemW));

    int blocks = (B + 127) / 128;
    ffjord_kernel<<<blocks, 128, sizeof(SmemW)>>>(z, dlp, W1, b1, W2, b2, W3, b3, out, B);
}

// round 5
// speedup vs baseline: 1.6338x; 1.2041x over previous
#include <cuda_runtime.h>

typedef unsigned long long ULL;

// ---------------- f32x2 helpers ----------------
__device__ __forceinline__ ULL pk2(float lo, float hi) {
    ULL r; asm("mov.b64 %0, {%1,%2};" : "=l"(r) : "f"(lo), "f"(hi)); return r;
}
__device__ __forceinline__ void upk2(ULL v, float& lo, float& hi) {
    asm("mov.b64 {%0,%1}, %2;" : "=f"(lo), "=f"(hi) : "l"(v));
}
__device__ __forceinline__ ULL fma2_(ULL a, ULL b, ULL c) {
    ULL d; asm("fma.rn.f32x2 %0, %1, %2, %3;" : "=l"(d) : "l"(a), "l"(b), "l"(c)); return d;
}
__device__ __forceinline__ ULL add2_(ULL a, ULL b) {
    ULL d; asm("add.rn.f32x2 %0, %1, %2;" : "=l"(d) : "l"(a), "l"(b)); return d;
}
__device__ __forceinline__ ULL mul2_(ULL a, ULL b) {
    ULL d; asm("mul.rn.f32x2 %0, %1, %2;" : "=l"(d) : "l"(a), "l"(b)); return d;
}

// ---------------- packed MUFU-free softplus + sigmoid (2 lanes) ----------------
__device__ __forceinline__ void act2(float xa, float xb, ULL& sp, ULL& sg)
{
    const ULL MAGIC = pk2(12582912.f, 12582912.f);
    const ULL NEG1  = pk2(-1.f, -1.f);
    const ULL ONE   = pk2(1.f, 1.f);
    const ULL TWO   = pk2(2.f, 2.f);
    const ULL C5 = pk2(1.33335581e-3f, 1.33335581e-3f);
    const ULL C4 = pk2(9.61812910e-3f, 9.61812910e-3f);
    const ULL C3 = pk2(5.55041087e-2f, 5.55041087e-2f);
    const ULL C2 = pk2(2.40226507e-1f, 2.40226507e-1f);
    const ULL C1 = pk2(6.93147182e-1f, 6.93147182e-1f);
    const ULL RI1 = pk2(-0.5f, -0.5f);
    const ULL RK1 = pk2(1.45710678f, 1.45710678f);
    const ULL RI2 = pk2(-0.16666667f, -0.16666667f);
    const ULL RK2 = pk2(0.82491498f, 0.82491498f);
    const ULL A7 = pk2(0.14285714f, 0.14285714f);
    const ULL A5 = pk2(0.2f, 0.2f);
    const ULL A3 = pk2(0.33333333f, 0.33333333f);

    float ya = fmaxf(fabsf(xa) * -1.4426950408889634f, -116.0f);
    float yb = fmaxf(fabsf(xb) * -1.4426950408889634f, -116.0f);
    ULL y  = pk2(ya, yb);
    ULL zz = add2_(y, MAGIC);
    ULL nf = fma2_(MAGIC, NEG1, zz);       // zz - MAGIC
    ULL f  = fma2_(nf, NEG1, y);           // y - nf, in [-0.5, 0.5]
    float za, zb2; upk2(zz, za, zb2);
    int ia = __float_as_int(za), ibt = __float_as_int(zb2);
    float sa = __int_as_float((int)(((unsigned)(ia  + (127 - 0x4B400000))) << 23));
    float sb = __int_as_float((int)(((unsigned)(ibt + (127 - 0x4B400000))) << 23));
    ULL scale = pk2(sa, sb);
    ULL p = fma2_(C5, f, C4);
    p = fma2_(p, f, C3);
    p = fma2_(p, f, C2);
    p = fma2_(p, f, C1);
    p = fma2_(p, f, ONE);
    ULL u = mul2_(p, scale);               // exp(-|x|) in (0,1]
    ULL d1 = add2_(u, ONE);
    ULL r1 = fma2_(d1, RI1, RK1);          // 1/(1+u): init + 2 Newton
    ULL nd1 = mul2_(d1, NEG1);
    ULL m;
    m = fma2_(nd1, r1, TWO); r1 = mul2_(r1, m);
    m = fma2_(nd1, r1, TWO); r1 = mul2_(r1, m);
    ULL d2 = add2_(u, TWO);
    ULL r2 = fma2_(d2, RI2, RK2);          // 1/(2+u): init + 2 Newton
    ULL nd2 = mul2_(d2, NEG1);
    m = fma2_(nd2, r2, TWO); r2 = mul2_(r2, m);
    m = fma2_(nd2, r2, TWO); r2 = mul2_(r2, m);
    ULL s  = mul2_(u, r2);                 // s in [0, 1/3]
    ULL s2 = mul2_(s, s);
    ULL q = fma2_(A7, s2, A5);
    q = fma2_(q, s2, A3);
    q = fma2_(q, s2, ONE);
    ULL l1p = mul2_(add2_(s, s), q);       // log1p(u)
    float mxa = fmaxf(xa, 0.f), mxb = fmaxf(xb, 0.f);
    sp = add2_(pk2(mxa, mxb), l1p);
    float ulo, uhi; upk2(u, ulo, uhi);
    float ga = (xa >= 0.f) ? 1.f : ulo;
    float gb = (xb >= 0.f) ? 1.f : uhi;
    sg = mul2_(r1, pk2(ga, gb));
}

// ---------------- shared-memory weight layout ----------------
// w2g block per jp (output pair j2=2jp, 2jp+1): 64 ulonglong2 entries,
//   index jp*64 + k2*4 + slot, slot = {P(2jp), P(2jp+1), TW(2jp), TW(2jp+1)}
//   P  = W2[j2][1+4k2 .. +3]                                (primal)
//   TW = P * (W3[0][1+j2]*W1[k][z0] + W3[1][1+j2]*W1[k][z1]) (folded tangent+W3)
struct SmemW {
    ulonglong2 w2g[32 * 64];                     // 32768 B
    ULL w1t[32], w1z0[32], w1z1[32], w1b[32];    // layer-1, packed unit pairs
    ULL w2tb[64];                                // {W2[j][0], b2[j]}
    ULL w3r0[32], w3r1[32];                      // packed W3 rows (z_dot epilogue)
    float w3t0, w3t1, b30, b31;
};

// ---------------- one dynamics evaluation ----------------
__device__ __forceinline__ void eval_dyn(const SmemW& sm, float t, float z0, float z1,
                                         float& k0, float& k1, float& kl)
{
    ULL s1p[32], sgp[32];   // packed {even, odd} softplus / sigmoid of layer-1
    ULL tp = pk2(t, t), z0p = pk2(z0, z0), z1p = pk2(z1, z1);
    #pragma unroll
    for (int k = 0; k < 32; ++k) {
        ULL x = fma2_(sm.w1t[k], tp, sm.w1b[k]);
        x = fma2_(sm.w1z0[k], z0p, x);
        x = fma2_(sm.w1z1[k], z1p, x);
        float xa, xb; upk2(x, xa, xb);
        act2(xa, xb, s1p[k], sgp[k]);
    }

    ULL Zd0 = 0ull, Zd1 = 0ull, Tr = 0ull;   // bit pattern 0 == {0.f, 0.f}

    #pragma unroll 1
    for (int jp = 0; jp < 32; ++jp) {        // output-unit pair (2jp, 2jp+1)
        const ulonglong2* r0 = &sm.w2g[jp * 64];
        ULL accp0 = 0ull, accp1 = 0ull;      // primal preacts
        ULL acct0 = 0ull, acct1 = 0ull;      // folded tangent (trace) preacts
        #pragma unroll
        for (int k2 = 0; k2 < 16; ++k2) {
            ulonglong2 P0 = r0[k2 * 4 + 0];
            ulonglong2 P1 = r0[k2 * 4 + 1];
            ulonglong2 T0 = r0[k2 * 4 + 2];
            ulonglong2 T1 = r0[k2 * 4 + 3];
            ULL se = s1p[2 * k2], so = s1p[2 * k2 + 1];
            ULL ge = sgp[2 * k2], go = sgp[2 * k2 + 1];
            accp0 = fma2_(P0.x, se, accp0);  accp0 = fma2_(P0.y, so, accp0);
            accp1 = fma2_(P1.x, se, accp1);  accp1 = fma2_(P1.y, so, accp1);
            acct0 = fma2_(T0.x, ge, acct0);  acct0 = fma2_(T0.y, go, acct0);
            acct1 = fma2_(T1.x, ge, acct1);  acct1 = fma2_(T1.y, go, acct1);
        }
        float w2ta, b2a; upk2(sm.w2tb[2 * jp],     w2ta, b2a);
        float w2tc, b2c; upk2(sm.w2tb[2 * jp + 1], w2tc, b2c);
        float pl, ph;
        upk2(accp0, pl, ph); float h20 = pl + ph + fmaf(w2ta, t, b2a);
        upk2(accp1, pl, ph); float h21 = pl + ph + fmaf(w2tc, t, b2c);
        upk2(acct0, pl, ph); float td0 = pl + ph;
        upk2(acct1, pl, ph); float td1 = pl + ph;
        ULL sp2, sg2;
        act2(h20, h21, sp2, sg2);
        Zd0 = fma2_(sm.w3r0[jp], sp2, Zd0);
        Zd1 = fma2_(sm.w3r1[jp], sp2, Zd1);
        Tr  = fma2_(sg2, pk2(td0, td1), Tr);
    }
    float a, b;
    upk2(Zd0, a, b); k0 = a + b + fmaf(sm.w3t0, t, sm.b30);
    upk2(Zd1, a, b); k1 = a + b + fmaf(sm.w3t1, t, sm.b31);
    upk2(Tr,  a, b); kl = -(a + b);
}

__global__ void __launch_bounds__(128, 2) ffjord_kernel(
    const float2* __restrict__ zin, const float* __restrict__ dlp,
    const float* __restrict__ W1, const float* __restrict__ b1,
    const float* __restrict__ W2, const float* __restrict__ b2,
    const float* __restrict__ W3, const float* __restrict__ b3,
    float* __restrict__ out, int B)
{
    extern __shared__ unsigned char smraw[];
    SmemW& sm = *reinterpret_cast<SmemW*>(smraw);
    int tid = threadIdx.x;

    // ---- stage weights into smem ----
    // 2048 ulonglong2 entries: jp*64 + k2*4 + slot
    for (int idx = tid; idx < 2048; idx += 128) {
        int jp   = idx >> 6;
        int rem  = idx & 63;
        int k2   = rem >> 2;
        int slot = rem & 3;
        int j2   = 2 * jp + (slot & 1);
        int bb   = 4 * k2;
        const float* wr = W2 + j2 * 65 + 1;          // skip time column
        float p0 = wr[bb + 0], p1 = wr[bb + 1], p2 = wr[bb + 2], p3 = wr[bb + 3];
        ulonglong2 E;
        if (slot < 2) {
            E.x = pk2(p0, p1); E.y = pk2(p2, p3);
        } else {
            float w30 = W3[1 + j2], w31 = W3[66 + j2];
            float t0 = fmaf(w30, W1[(bb + 0) * 3 + 1], w31 * W1[(bb + 0) * 3 + 2]);
            float t1 = fmaf(w30, W1[(bb + 1) * 3 + 1], w31 * W1[(bb + 1) * 3 + 2]);
            float t2 = fmaf(w30, W1[(bb + 2) * 3 + 1], w31 * W1[(bb + 2) * 3 + 2]);
            float t3 = fmaf(w30, W1[(bb + 3) * 3 + 1], w31 * W1[(bb + 3) * 3 + 2]);
            E.x = pk2(p0 * t0, p1 * t1); E.y = pk2(p2 * t2, p3 * t3);
        }
        sm.w2g[idx] = E;
    }
    if (tid < 32) {
        int k = tid;                                  // unit pair (2k, 2k+1)
        sm.w1t[k]  = pk2(W1[(2 * k) * 3 + 0], W1[(2 * k + 1) * 3 + 0]);
        sm.w1z0[k] = pk2(W1[(2 * k) * 3 + 1], W1[(2 * k + 1) * 3 + 1]);
        sm.w1z1[k] = pk2(W1[(2 * k) * 3 + 2], W1[(2 * k + 1) * 3 + 2]);
        sm.w1b[k]  = pk2(b1[2 * k], b1[2 * k + 1]);
        sm.w3r0[k] = pk2(W3[1 + 2 * k],  W3[2 + 2 * k]);
        sm.w3r1[k] = pk2(W3[66 + 2 * k], W3[67 + 2 * k]);
    } else if (tid < 96) {
        int j = tid - 32;
        sm.w2tb[j] = pk2(W2[j * 65 + 0], b2[j]);
    }
    if (tid == 0) { sm.w3t0 = W3[0]; sm.w3t1 = W3[65]; sm.b30 = b3[0]; sm.b31 = b3[1]; }
    __syncthreads();

    int gid = blockIdx.x * 128 + tid;
    if (gid >= B) return;
    float2 zv = zin[gid];
    float z0 = zv.x, z1 = zv.y;
    float lp = dlp[gid];

    const float dt = 0.25f;
    #pragma unroll 1
    for (int step = 0; step < 4; ++step) {
        float tb = (float)step * dt;
        float acc0 = 0.0f, acc1 = 0.0f, accl = 0.0f;
        float pk0v = 0.0f, pk1v = 0.0f;
        #pragma unroll 1
        for (int s = 0; s < 4; ++s) {
            float cs = (s == 0) ? 0.0f : ((s == 3) ? dt : 0.5f * dt);
            float ws = (s == 1 || s == 2) ? 2.0f : 1.0f;
            float te = tb + cs;
            float i0 = fmaf(cs, pk0v, z0);
            float i1 = fmaf(cs, pk1v, z1);
            float k0, k1, klv;
            eval_dyn(sm, te, i0, i1, k0, k1, klv);
            acc0 = fmaf(ws, k0, acc0);
            acc1 = fmaf(ws, k1, acc1);
            accl = fmaf(ws, klv, accl);
            pk0v = k0; pk1v = k1;
        }
        const float c6 = dt / 6.0f;
        z0 = fmaf(c6, acc0, z0);
        z1 = fmaf(c6, acc1, z1);
        lp = fmaf(c6, accl, lp);
    }

    reinterpret_cast<float2*>(out)[gid] = make_float2(z0, z1);  // zf: (B,2)
    out[2 * B + gid] = lp;                                      // delta_logpz: (B,1)
}

extern "C" void kernel_launch(void* const* d_in, const int* in_sizes, int n_in,
                              void* d_out, int out_size) {
    const float2* z  = (const float2*)d_in[0];
    const float* dlp = (const float*)d_in[1];
    const float* W1  = (const float*)d_in[2];
    const float* b1  = (const float*)d_in[3];
    const float* W2  = (const float*)d_in[4];
    const float* b2  = (const float*)d_in[5];
    const float* W3  = (const float*)d_in[6];
    const float* b3  = (const float*)d_in[7];
    float* out = (float*)d_out;
    int B = in_sizes[0] / 2;

    // Host-side, enqueues nothing -> graph-capture safe. Idempotent.
    cudaFuncSetAttribute(ffjord_kernel, cudaFuncAttributeMaxDynamicSharedMemorySize,
                         (int)sizeof(SmemW));

    int blocks = (B + 127) / 128;
    ffjord_kernel<<<blocks, 128, sizeof(SmemW)>>>(z, dlp, W1, b1, W2, b2, W3, b3, out, B);
}

// round 6
// speedup vs baseline: 2.4306x; 1.4877x over previous
#include <cuda_runtime.h>

typedef unsigned long long ULL;

// ---------------- f32x2 helpers ----------------
__device__ __forceinline__ ULL pk2(float lo, float hi) {
    ULL r; asm("mov.b64 %0, {%1,%2};" : "=l"(r) : "f"(lo), "f"(hi)); return r;
}
__device__ __forceinline__ void upk2(ULL v, float& lo, float& hi) {
    asm("mov.b64 {%0,%1}, %2;" : "=f"(lo), "=f"(hi) : "l"(v));
}
__device__ __forceinline__ ULL fma2_(ULL a, ULL b, ULL c) {
    ULL d; asm("fma.rn.f32x2 %0, %1, %2, %3;" : "=l"(d) : "l"(a), "l"(b), "l"(c)); return d;
}
__device__ __forceinline__ ULL add2_(ULL a, ULL b) {
    ULL d; asm("add.rn.f32x2 %0, %1, %2;" : "=l"(d) : "l"(a), "l"(b)); return d;
}
__device__ __forceinline__ ULL mul2_(ULL a, ULL b) {
    ULL d; asm("mul.rn.f32x2 %0, %1, %2;" : "=l"(d) : "l"(a), "l"(b)); return d;
}

// ---------------- packed MUFU-free softplus + sigmoid (2 lanes) ----------------
__device__ __forceinline__ void act2(float xa, float xb, ULL& sp, ULL& sg)
{
    const ULL MAGIC = pk2(12582912.f, 12582912.f);
    const ULL NEG1  = pk2(-1.f, -1.f);
    const ULL ONE   = pk2(1.f, 1.f);
    const ULL TWO   = pk2(2.f, 2.f);
    const ULL C5 = pk2(1.33335581e-3f, 1.33335581e-3f);
    const ULL C4 = pk2(9.61812910e-3f, 9.61812910e-3f);
    const ULL C3 = pk2(5.55041087e-2f, 5.55041087e-2f);
    const ULL C2 = pk2(2.40226507e-1f, 2.40226507e-1f);
    const ULL C1 = pk2(6.93147182e-1f, 6.93147182e-1f);
    const ULL RI1 = pk2(-0.5f, -0.5f);
    const ULL RK1 = pk2(1.45710678f, 1.45710678f);
    const ULL RI2 = pk2(-0.16666667f, -0.16666667f);
    const ULL RK2 = pk2(0.82491498f, 0.82491498f);
    const ULL A7 = pk2(0.14285714f, 0.14285714f);
    const ULL A5 = pk2(0.2f, 0.2f);
    const ULL A3 = pk2(0.33333333f, 0.33333333f);

    float ya = fmaxf(fabsf(xa) * -1.4426950408889634f, -116.0f);
    float yb = fmaxf(fabsf(xb) * -1.4426950408889634f, -116.0f);
    ULL y  = pk2(ya, yb);
    ULL zz = add2_(y, MAGIC);
    ULL nf = fma2_(MAGIC, NEG1, zz);       // zz - MAGIC
    ULL f  = fma2_(nf, NEG1, y);           // y - nf, in [-0.5, 0.5]
    float za, zb2; upk2(zz, za, zb2);
    int ia = __float_as_int(za), ibt = __float_as_int(zb2);
    float sa = __int_as_float((int)(((unsigned)(ia  + (127 - 0x4B400000))) << 23));
    float sb = __int_as_float((int)(((unsigned)(ibt + (127 - 0x4B400000))) << 23));
    ULL scale = pk2(sa, sb);
    ULL p = fma2_(C5, f, C4);
    p = fma2_(p, f, C3);
    p = fma2_(p, f, C2);
    p = fma2_(p, f, C1);
    p = fma2_(p, f, ONE);
    ULL u = mul2_(p, scale);               // exp(-|x|) in (0,1]
    ULL d1 = add2_(u, ONE);
    ULL r1 = fma2_(d1, RI1, RK1);          // 1/(1+u): init + 2 Newton
    ULL nd1 = mul2_(d1, NEG1);
    ULL m;
    m = fma2_(nd1, r1, TWO); r1 = mul2_(r1, m);
    m = fma2_(nd1, r1, TWO); r1 = mul2_(r1, m);
    ULL d2 = add2_(u, TWO);
    ULL r2 = fma2_(d2, RI2, RK2);          // 1/(2+u): init + 2 Newton
    ULL nd2 = mul2_(d2, NEG1);
    m = fma2_(nd2, r2, TWO); r2 = mul2_(r2, m);
    m = fma2_(nd2, r2, TWO); r2 = mul2_(r2, m);
    ULL s  = mul2_(u, r2);                 // s in [0, 1/3]
    ULL s2 = mul2_(s, s);
    ULL q = fma2_(A7, s2, A5);
    q = fma2_(q, s2, A3);
    q = fma2_(q, s2, ONE);
    ULL l1p = mul2_(add2_(s, s), q);       // log1p(u)
    float mxa = fmaxf(xa, 0.f), mxb = fmaxf(xb, 0.f);
    sp = add2_(pk2(mxa, mxb), l1p);
    float ulo, uhi; upk2(u, ulo, uhi);
    float ga = (xa >= 0.f) ? 1.f : ulo;
    float gb = (xb >= 0.f) ? 1.f : uhi;
    sg = mul2_(r1, pk2(ga, gb));
}

// ---------------- shared-memory layout ----------------
// w2g block per jp (output pair j2=2jp, 2jp+1): 64 ulonglong2 entries,
//   index jp*64 + k2*4 + slot, slot = {P(2jp), P(2jp+1), TW(2jp), TW(2jp+1)}
//   P  = W2[j2][1+4k2 .. +3]                                 (primal)
//   TW = P * (W3[0][1+j2]*W1[k][z0] + W3[1][1+j2]*W1[k][z1]) (folded tangent+W3)
// actsg: per-thread sigmoid activations [k-pair][tid], conflict-free LDS.64.
struct SmemW {
    ulonglong2 w2g[32 * 64];                     // 32768 B
    ULL actsg[32 * 128];                         // 32768 B (per-thread scratch)
    ULL w1t[32], w1z0[32], w1z1[32], w1b[32];    // layer-1, packed unit pairs
    ULL w2tb[64];                                // {W2[j][0], b2[j]}
    ULL w3r0[32], w3r1[32];                      // packed W3 rows (z_dot epilogue)
    float w3t0, w3t1, b30, b31;
};

// ---------------- one dynamics evaluation ----------------
__device__ __forceinline__ void eval_dyn(SmemW& sm, int tid, float t, float z0, float z1,
                                         float& k0, float& k1, float& kl)
{
    ULL s1p[32];            // packed softplus of layer-1 (regs); sigmoid -> smem
    ULL tp = pk2(t, t), z0p = pk2(z0, z0), z1p = pk2(z1, z1);
    #pragma unroll
    for (int k = 0; k < 32; ++k) {
        ULL x = fma2_(sm.w1t[k], tp, sm.w1b[k]);
        x = fma2_(sm.w1z0[k], z0p, x);
        x = fma2_(sm.w1z1[k], z1p, x);
        float xa, xb; upk2(x, xa, xb);
        ULL sg;
        act2(xa, xb, s1p[k], sg);
        sm.actsg[k * 128 + tid] = sg;      // private column, no sync needed
    }

    ULL Zd0 = 0ull, Zd1 = 0ull, Tr = 0ull;   // bit pattern 0 == {0.f, 0.f}

    // Tile of 4 output-unit pairs (8 units): activation loads amortized x4.
    #pragma unroll 1
    for (int jt = 0; jt < 8; ++jt) {
        ULL accp[8], acct[8];
        #pragma unroll
        for (int u = 0; u < 8; ++u) { accp[u] = 0ull; acct[u] = 0ull; }
        const ulonglong2* rb = &sm.w2g[jt * 256];
        #pragma unroll
        for (int k2 = 0; k2 < 16; ++k2) {
            ULL se = s1p[2 * k2], so = s1p[2 * k2 + 1];
            ULL ge = sm.actsg[(2 * k2) * 128 + tid];
            ULL go = sm.actsg[(2 * k2 + 1) * 128 + tid];
            #pragma unroll
            for (int u = 0; u < 4; ++u) {
                const ulonglong2* r = &rb[u * 64 + k2 * 4];
                ulonglong2 P0 = r[0];
                ulonglong2 P1 = r[1];
                ulonglong2 T0 = r[2];
                ulonglong2 T1 = r[3];
                accp[2*u]   = fma2_(P0.x, se, accp[2*u]);
                accp[2*u]   = fma2_(P0.y, so, accp[2*u]);
                accp[2*u+1] = fma2_(P1.x, se, accp[2*u+1]);
                accp[2*u+1] = fma2_(P1.y, so, accp[2*u+1]);
                acct[2*u]   = fma2_(T0.x, ge, acct[2*u]);
                acct[2*u]   = fma2_(T0.y, go, acct[2*u]);
                acct[2*u+1] = fma2_(T1.x, ge, acct[2*u+1]);
                acct[2*u+1] = fma2_(T1.y, go, acct[2*u+1]);
            }
        }
        #pragma unroll
        for (int u = 0; u < 4; ++u) {
            int jp = jt * 4 + u;
            float w2ta, b2a; upk2(sm.w2tb[2 * jp],     w2ta, b2a);
            float w2tc, b2c; upk2(sm.w2tb[2 * jp + 1], w2tc, b2c);
            float pl, ph;
            upk2(accp[2*u],   pl, ph); float h20 = pl + ph + fmaf(w2ta, t, b2a);
            upk2(accp[2*u+1], pl, ph); float h21 = pl + ph + fmaf(w2tc, t, b2c);
            upk2(acct[2*u],   pl, ph); float td0 = pl + ph;
            upk2(acct[2*u+1], pl, ph); float td1 = pl + ph;
            ULL sp2, sg2;
            act2(h20, h21, sp2, sg2);
            Zd0 = fma2_(sm.w3r0[jp], sp2, Zd0);
            Zd1 = fma2_(sm.w3r1[jp], sp2, Zd1);
            Tr  = fma2_(sg2, pk2(td0, td1), Tr);
        }
    }
    float a, b;
    upk2(Zd0, a, b); k0 = a + b + fmaf(sm.w3t0, t, sm.b30);
    upk2(Zd1, a, b); k1 = a + b + fmaf(sm.w3t1, t, sm.b31);
    upk2(Tr,  a, b); kl = -(a + b);
}

__global__ void __launch_bounds__(128, 3) ffjord_kernel(
    const float2* __restrict__ zin, const float* __restrict__ dlp,
    const float* __restrict__ W1, const float* __restrict__ b1,
    const float* __restrict__ W2, const float* __restrict__ b2,
    const float* __restrict__ W3, const float* __restrict__ b3,
    float* __restrict__ out, int B)
{
    extern __shared__ unsigned char smraw[];
    SmemW& sm = *reinterpret_cast<SmemW*>(smraw);
    int tid = threadIdx.x;

    // ---- stage weights into smem ----
    for (int idx = tid; idx < 2048; idx += 128) {
        int jp   = idx >> 6;
        int rem  = idx & 63;
        int k2   = rem >> 2;
        int slot = rem & 3;
        int j2   = 2 * jp + (slot & 1);
        int bb   = 4 * k2;
        const float* wr = W2 + j2 * 65 + 1;          // skip time column
        float p0 = wr[bb + 0], p1 = wr[bb + 1], p2 = wr[bb + 2], p3 = wr[bb + 3];
        ulonglong2 E;
        if (slot < 2) {
            E.x = pk2(p0, p1); E.y = pk2(p2, p3);
        } else {
            float w30 = W3[1 + j2], w31 = W3[66 + j2];
            float t0 = fmaf(w30, W1[(bb + 0) * 3 + 1], w31 * W1[(bb + 0) * 3 + 2]);
            float t1 = fmaf(w30, W1[(bb + 1) * 3 + 1], w31 * W1[(bb + 1) * 3 + 2]);
            float t2 = fmaf(w30, W1[(bb + 2) * 3 + 1], w31 * W1[(bb + 2) * 3 + 2]);
            float t3 = fmaf(w30, W1[(bb + 3) * 3 + 1], w31 * W1[(bb + 3) * 3 + 2]);
            E.x = pk2(p0 * t0, p1 * t1); E.y = pk2(p2 * t2, p3 * t3);
        }
        sm.w2g[idx] = E;
    }
    if (tid < 32) {
        int k = tid;                                  // unit pair (2k, 2k+1)
        sm.w1t[k]  = pk2(W1[(2 * k) * 3 + 0], W1[(2 * k + 1) * 3 + 0]);
        sm.w1z0[k] = pk2(W1[(2 * k) * 3 + 1], W1[(2 * k + 1) * 3 + 1]);
        sm.w1z1[k] = pk2(W1[(2 * k) * 3 + 2], W1[(2 * k + 1) * 3 + 2]);
        sm.w1b[k]  = pk2(b1[2 * k], b1[2 * k + 1]);
        sm.w3r0[k] = pk2(W3[1 + 2 * k],  W3[2 + 2 * k]);
        sm.w3r1[k] = pk2(W3[66 + 2 * k], W3[67 + 2 * k]);
    } else if (tid < 96) {
        int j = tid - 32;
        sm.w2tb[j] = pk2(W2[j * 65 + 0], b2[j]);
    }
    if (tid == 0) { sm.w3t0 = W3[0]; sm.w3t1 = W3[65]; sm.b30 = b3[0]; sm.b31 = b3[1]; }
    __syncthreads();

    int gid = blockIdx.x * 128 + tid;
    if (gid >= B) return;
    float2 zv = zin[gid];
    float z0 = zv.x, z1 = zv.y;
    float lp = dlp[gid];

    const float dt = 0.25f;
    #pragma unroll 1
    for (int step = 0; step < 4; ++step) {
        float tb = (float)step * dt;
        float acc0 = 0.0f, acc1 = 0.0f, accl = 0.0f;
        float pk0v = 0.0f, pk1v = 0.0f;
        #pragma unroll 1
        for (int s = 0; s < 4; ++s) {
            float cs = (s == 0) ? 0.0f : ((s == 3) ? dt : 0.5f * dt);
            float ws = (s == 1 || s == 2) ? 2.0f : 1.0f;
            float te = tb + cs;
            float i0 = fmaf(cs, pk0v, z0);
            float i1 = fmaf(cs, pk1v, z1);
            float k0, k1, klv;
            eval_dyn(sm, tid, te, i0, i1, k0, k1, klv);
            acc0 = fmaf(ws, k0, acc0);
            acc1 = fmaf(ws, k1, acc1);
            accl = fmaf(ws, klv, accl);
            pk0v = k0; pk1v = k1;
        }
        const float c6 = dt / 6.0f;
        z0 = fmaf(c6, acc0, z0);
        z1 = fmaf(c6, acc1, z1);
        lp = fmaf(c6, accl, lp);
    }

    reinterpret_cast<float2*>(out)[gid] = make_float2(z0, z1);  // zf: (B,2)
    out[2 * B + gid] = lp;                                      // delta_logpz: (B,1)
}

extern "C" void kernel_launch(void* const* d_in, const int* in_sizes, int n_in,
                              void* d_out, int out_size) {
    const float2* z  = (const float2*)d_in[0];
    const float* dlp = (const float*)d_in[1];
    const float* W1  = (const float*)d_in[2];
    const float* b1  = (const float*)d_in[3];
    const float* W2  = (const float*)d_in[4];
    const float* b2  = (const float*)d_in[5];
    const float* W3  = (const float*)d_in[6];
    const float* b3  = (const float*)d_in[7];
    float* out = (float*)d_out;
    int B = in_sizes[0] / 2;

    // Host-side, enqueues nothing -> graph-capture safe. Idempotent.
    cudaFuncSetAttribute(ffjord_kernel, cudaFuncAttributeMaxDynamicSharedMemorySize,
                         (int)sizeof(SmemW));

    int blocks = (B + 127) / 128;
    ffjord_kernel<<<blocks, 128, sizeof(SmemW)>>>(z, dlp, W1, b1, W2, b2, W3, b3, out, B);
}